// round 4
// baseline (speedup 1.0000x reference)
#include <cuda_runtime.h>

// NNSystem_mech RHS: 2-component neural ODE right-hand side.
// Entire computation is scalar-sized; one warp, one launch, latency-bound.

__device__ __forceinline__ float softplus_f(float x) {
    // jax.nn.softplus(x) = log1p(exp(x)), stable form:
    return fmaxf(x, 0.0f) + log1pf(__expf(-fabsf(x)));
}

__global__ void nnsys_kernel(
    const float* __restrict__ y,       // (2,)
    const float* __restrict__ aiw, const float* __restrict__ aib,     // (2,1),(2,)
    const float* __restrict__ apw1, const float* __restrict__ apb1,   // (10,1),(10,)
    const float* __restrict__ apw2, const float* __restrict__ apb2,   // (1,10),(1,)
    const float* __restrict__ anw1, const float* __restrict__ anb1,
    const float* __restrict__ anw2, const float* __restrict__ anb2,
    const float* __restrict__ arw,  const float* __restrict__ arb,    // (1,2),(1,)
    const float* __restrict__ ciw,  const float* __restrict__ cib,
    const float* __restrict__ cpw1, const float* __restrict__ cpb1,
    const float* __restrict__ cpw2, const float* __restrict__ cpb2,
    const float* __restrict__ cnw1, const float* __restrict__ cnb1,
    const float* __restrict__ cnw2, const float* __restrict__ cnb2,
    const float* __restrict__ crw,  const float* __restrict__ crb,
    const float* __restrict__ K_i,  const float* __restrict__ n_hill,
    float* __restrict__ out)           // (2,)
{
    const int j = threadIdx.x;  // 0..31

    const float y0 = y[0];
    const float y1 = y[1];

    // initial 1->2 linears + softplus (computed redundantly on all lanes; cheap)
    const float a0 = softplus_f(fmaf(aiw[0], y0, aib[0]));
    const float a1 = softplus_f(fmaf(aiw[1], y0, aib[1]));
    const float c0 = softplus_f(fmaf(ciw[0], y1, cib[0]));
    const float c1 = softplus_f(fmaf(ciw[1], y1, cib[1]));

    // four tiny MLPs (1->10->1): lane j<10 owns hidden unit j of each MLP
    float ap = 0.0f, an = 0.0f, cp = 0.0f, cn = 0.0f;
    if (j < 10) {
        ap = apw2[j] * softplus_f(fmaf(apw1[j], a0, apb1[j]));
        an = anw2[j] * softplus_f(fmaf(anw1[j], a1, anb1[j]));
        cp = cpw2[j] * softplus_f(fmaf(cpw1[j], c0, cpb1[j]));
        cn = cnw2[j] * softplus_f(fmaf(cnw1[j], c1, cnb1[j]));
    }

    // butterfly reduction across the warp (lanes >= 10 contribute zero)
    #pragma unroll
    for (int ofs = 16; ofs > 0; ofs >>= 1) {
        ap += __shfl_xor_sync(0xFFFFFFFFu, ap, ofs);
        an += __shfl_xor_sync(0xFFFFFFFFu, an, ofs);
        cp += __shfl_xor_sync(0xFFFFFFFFu, cp, ofs);
        cn += __shfl_xor_sync(0xFFFFFFFFu, cn, ofs);
    }

    if (j == 0) {
        const float a_pos = ap + apb2[0];
        const float a_neg = an + anb2[0];
        const float c_pos = cp + cpb2[0];
        const float c_neg = cn + cnb2[0];

        // Hill inhibition: Kn / (Kn + y1^n); K_i=1.5>0, y1 in (0,1) -> __powf safe
        const float nH = n_hill[0];
        const float Kn = __powf(K_i[0], nH);
        const float hill = Kn / (Kn + __powf(y1, nH));

        const float dy_acth = fmaf(arw[0], softplus_f(hill * a_pos),
                              fmaf(arw[1], softplus_f(a_neg), arb[0]));
        const float dy_cort = fmaf(crw[0], softplus_f(y0 * c_pos),
                              fmaf(crw[1], softplus_f(c_neg), crb[0]));

        out[0] = dy_acth;
        out[1] = dy_cort;
    }
}

extern "C" void kernel_launch(void* const* d_in, const int* in_sizes, int n_in,
                              void* d_out, int out_size) {
    // metadata order mirrors reference() signature:
    //  0:t 1:y 2:aiw 3:aib 4:apw1 5:apb1 6:apw2 7:apb2
    //  8:anw1 9:anb1 10:anw2 11:anb2 12:arw 13:arb
    // 14:ciw 15:cib 16:cpw1 17:cpb1 18:cpw2 19:cpb2
    // 20:cnw1 21:cnb1 22:cnw2 23:cnb2 24:crw 25:crb 26:K_i 27:n_hill
    const float* y    = (const float*)d_in[1];
    const float* aiw  = (const float*)d_in[2];
    const float* aib  = (const float*)d_in[3];
    const float* apw1 = (const float*)d_in[4];
    const float* apb1 = (const float*)d_in[5];
    const float* apw2 = (const float*)d_in[6];
    const float* apb2 = (const float*)d_in[7];
    const float* anw1 = (const float*)d_in[8];
    const float* anb1 = (const float*)d_in[9];
    const float* anw2 = (const float*)d_in[10];
    const float* anb2 = (const float*)d_in[11];
    const float* arw  = (const float*)d_in[12];
    const float* arb  = (const float*)d_in[13];
    const float* ciw  = (const float*)d_in[14];
    const float* cib  = (const float*)d_in[15];
    const float* cpw1 = (const float*)d_in[16];
    const float* cpb1 = (const float*)d_in[17];
    const float* cpw2 = (const float*)d_in[18];
    const float* cpb2 = (const float*)d_in[19];
    const float* cnw1 = (const float*)d_in[20];
    const float* cnb1 = (const float*)d_in[21];
    const float* cnw2 = (const float*)d_in[22];
    const float* cnb2 = (const float*)d_in[23];
    const float* crw  = (const float*)d_in[24];
    const float* crb  = (const float*)d_in[25];
    const float* K_i  = (const float*)d_in[26];
    const float* nh   = (const float*)d_in[27];

    nnsys_kernel<<<1, 32>>>(y, aiw, aib, apw1, apb1, apw2, apb2,
                            anw1, anb1, anw2, anb2, arw, arb,
                            ciw, cib, cpw1, cpb1, cpw2, cpb2,
                            cnw1, cnb1, cnw2, cnb2, crw, crb,
                            K_i, nh, (float*)d_out);
}

// round 5
// speedup vs baseline: 1.0155x; 1.0155x over previous
#include <cuda_runtime.h>

// NNSystem_mech RHS: scalar-sized neural-ODE right-hand side.
// One warp, one launch. Latency-bound: optimize the serial dependency chain.
//   - 4-step butterfly (lanes 10..31 zero; offsets <16 never touch upper half)
//   - Hill term computed on all lanes BEFORE the reduction (MUFU overlaps SHFL)
//   - epilogue split across lanes 0/1 (butterfly leaves sums in all low lanes)
//   - fast stable softplus via __expf/__logf (rel err ~1e-6 << 1e-3 tolerance)

__device__ __forceinline__ float sp(float x) {
    // stable softplus: max(x,0) + log(1 + exp(-|x|)); arg of log in (1,2] -> __logf safe
    return fmaxf(x, 0.0f) + __logf(1.0f + __expf(-fabsf(x)));
}

__global__ void __launch_bounds__(32, 1) nnsys_kernel(
    const float* __restrict__ y,
    const float* __restrict__ aiw, const float* __restrict__ aib,
    const float* __restrict__ apw1, const float* __restrict__ apb1,
    const float* __restrict__ apw2, const float* __restrict__ apb2,
    const float* __restrict__ anw1, const float* __restrict__ anb1,
    const float* __restrict__ anw2, const float* __restrict__ anb2,
    const float* __restrict__ arw,  const float* __restrict__ arb,
    const float* __restrict__ ciw,  const float* __restrict__ cib,
    const float* __restrict__ cpw1, const float* __restrict__ cpb1,
    const float* __restrict__ cpw2, const float* __restrict__ cpb2,
    const float* __restrict__ cnw1, const float* __restrict__ cnb1,
    const float* __restrict__ cnw2, const float* __restrict__ cnb2,
    const float* __restrict__ crw,  const float* __restrict__ crb,
    const float* __restrict__ K_i,  const float* __restrict__ n_hill,
    float* __restrict__ out)
{
    const int j = threadIdx.x;

    // Front-batch every scalar load so all global latency overlaps (MLP>=1 trip).
    const float y0 = y[0];
    const float y1 = y[1];
    const float apb2v = apb2[0], anb2v = anb2[0];
    const float cpb2v = cpb2[0], cnb2v = cnb2[0];
    const float arw0 = arw[0], arw1 = arw[1], arbv = arb[0];
    const float crw0 = crw[0], crw1 = crw[1], crbv = crb[0];
    const float Kv = K_i[0], nH = n_hill[0];

    // initial 1->2 linears + softplus (redundant on all lanes)
    const float a0 = sp(fmaf(aiw[0], y0, aib[0]));
    const float a1 = sp(fmaf(aiw[1], y0, aib[1]));
    const float c0 = sp(fmaf(ciw[0], y1, cib[0]));
    const float c1 = sp(fmaf(ciw[1], y1, cib[1]));

    // four tiny MLPs: lane j<10 owns hidden unit j of each
    float ap = 0.0f, an = 0.0f, cp = 0.0f, cn = 0.0f;
    if (j < 10) {
        ap = apw2[j] * sp(fmaf(apw1[j], a0, apb1[j]));
        an = anw2[j] * sp(fmaf(anw1[j], a1, anb1[j]));
        cp = cpw2[j] * sp(fmaf(cpw1[j], c0, cpb1[j]));
        cn = cnw2[j] * sp(fmaf(cnw1[j], c1, cnb1[j]));
    }

    // Hill term: independent of the reduction -> issue its MUFU chain now so it
    // completes while the SHFL butterfly runs. K=1.5>0, y1 in (0,1): __powf safe.
    const float Kn = __powf(Kv, nH);
    const float hill = Kn / (Kn + __powf(y1, nH));

    // 4-step butterfly: lanes 10..15 carry zeros; offsets <16 confine exchange
    // to the lower half, so lanes 0/1 end with the exact 10-element sums.
    #pragma unroll
    for (int ofs = 8; ofs > 0; ofs >>= 1) {
        ap += __shfl_xor_sync(0xFFFFFFFFu, ap, ofs);
        an += __shfl_xor_sync(0xFFFFFFFFu, an, ofs);
        cp += __shfl_xor_sync(0xFFFFFFFFu, cp, ofs);
        cn += __shfl_xor_sync(0xFFFFFFFFu, cn, ofs);
    }

    // Epilogue split across two lanes: each runs its own 2-softplus chain.
    if (j < 2) {
        const bool acth = (j == 0);
        const float pos = acth ? hill * (ap + apb2v) : y0 * (cp + cpb2v);
        const float neg = acth ? (an + anb2v)        : (cn + cnb2v);
        const float w0  = acth ? arw0 : crw0;
        const float w1  = acth ? arw1 : crw1;
        const float b   = acth ? arbv : crbv;
        out[j] = fmaf(w0, sp(pos), fmaf(w1, sp(neg), b));
    }
}

extern "C" void kernel_launch(void* const* d_in, const int* in_sizes, int n_in,
                              void* d_out, int out_size) {
    // metadata order mirrors reference() signature:
    //  0:t 1:y 2:aiw 3:aib 4:apw1 5:apb1 6:apw2 7:apb2
    //  8:anw1 9:anb1 10:anw2 11:anb2 12:arw 13:arb
    // 14:ciw 15:cib 16:cpw1 17:cpb1 18:cpw2 19:cpb2
    // 20:cnw1 21:cnb1 22:cnw2 23:cnb2 24:crw 25:crb 26:K_i 27:n_hill
    nnsys_kernel<<<1, 32>>>(
        (const float*)d_in[1],
        (const float*)d_in[2],  (const float*)d_in[3],
        (const float*)d_in[4],  (const float*)d_in[5],
        (const float*)d_in[6],  (const float*)d_in[7],
        (const float*)d_in[8],  (const float*)d_in[9],
        (const float*)d_in[10], (const float*)d_in[11],
        (const float*)d_in[12], (const float*)d_in[13],
        (const float*)d_in[14], (const float*)d_in[15],
        (const float*)d_in[16], (const float*)d_in[17],
        (const float*)d_in[18], (const float*)d_in[19],
        (const float*)d_in[20], (const float*)d_in[21],
        (const float*)d_in[22], (const float*)d_in[23],
        (const float*)d_in[24], (const float*)d_in[25],
        (const float*)d_in[26], (const float*)d_in[27],
        (float*)d_out);
}